// round 3
// baseline (speedup 1.0000x reference)
#include <cuda_runtime.h>
#include <math.h>

#define RIR_LENGTH 3968
#define PAD        40
#define NTAP       80          // tap n=+40 is always exactly zero (Hann edge)
#define BATCH      128
#define MAXO       15
#define GRID_N     31
#define GRID_TOT   (31*31*31)  // 29791
#define NIMG       4991        // |x|+|y|+|z| <= 15 lattice points
#define FSR        46.64723032f   // fp32(16000/343)
#define INV_PI     0.3183098862f
#define CR_STEP    0.9969173337f  // cos(pi/40)
#define SR_STEP    0.0784590957f  // sin(pi/40)

__device__ int g_xyz[NIMG + 8];
__device__ int g_cnt;

// ---------------------------------------------------------------------------
__global__ void k_reset() { g_cnt = 0; }

__global__ void k_build() {
    int idx = blockIdx.x * blockDim.x + threadIdx.x;
    if (idx >= GRID_TOT) return;
    int ix = idx % GRID_N - MAXO;
    int iy = (idx / GRID_N) % GRID_N - MAXO;
    int iz = idx / (GRID_N * GRID_N) - MAXO;
    if (abs(ix) + abs(iy) + abs(iz) <= MAXO) {
        int p = atomicAdd(&g_cnt, 1);
        if (p < NIMG)
            g_xyz[p] = (ix + 16) | ((iy + 16) << 8) | ((iz + 16) << 16);
    }
}

// Zero the rir region of d_out and compute toa.
__global__ void k_init(const float* __restrict__ inp, float* __restrict__ out) {
    int i = blockIdx.x * blockDim.x + threadIdx.x;
    int total = BATCH * RIR_LENGTH;
    for (int j = i; j < total; j += gridDim.x * blockDim.x) out[j] = 0.0f;
    if (i < BATCH) {
        const float* r = inp + i * 12;
        float dx = __fmul_rn(__fsub_rn(__fmul_rn(r[3], r[0]), __fmul_rn(r[6], r[0])), 1.0f);
        float dy = __fsub_rn(__fmul_rn(r[4], r[1]), __fmul_rn(r[7], r[1]));
        float dz = __fsub_rn(__fmul_rn(r[5], r[2]), __fmul_rn(r[8], r[2]));
        dx = __fsub_rn(__fmul_rn(r[3], r[0]), __fmul_rn(r[6], r[0]));
        float ss = __fadd_rn(__fadd_rn(__fmul_rn(dx, dx), __fmul_rn(dy, dy)),
                             __fmul_rn(dz, dz));
        float dist = __fsqrt_rn(ss);
        out[total + i] = __fadd_rn((float)PAD, __fmul_rn(dist, FSR));
    }
}

// ---------------------------------------------------------------------------
#define TPB   256
#define SPLIT 4

__global__ __launch_bounds__(TPB) void k_main(const float* __restrict__ inp,
                                              float* __restrict__ out) {
    __shared__ float srir[RIR_LENGTH];
    __shared__ float sPW[16];          // trw^e, e = 0..15   (|ix|+|iy| <= 15)
    __shared__ float sPL[9];           // tr_zlo^e, e = 0..8
    __shared__ float sPH[9];           // tr_zhi^e, e = 0..8
    __shared__ float sGeo[9];          // room[3], mic[3], src[3]

    const int b     = blockIdx.y;
    const int split = blockIdx.x;
    const int tid   = threadIdx.x;

    for (int j = tid; j < RIR_LENGTH; j += TPB) srir[j] = 0.0f;

    if (tid == 0) {
        const float* r = inp + b * 12;
        float rx = r[0], ry = r[1], rz = r[2];
        sGeo[0] = rx;                  sGeo[1] = ry;                  sGeo[2] = rz;
        sGeo[3] = __fmul_rn(r[3], rx); sGeo[4] = __fmul_rn(r[4], ry); sGeo[5] = __fmul_rn(r[5], rz);
        sGeo[6] = __fmul_rn(r[6], rx); sGeo[7] = __fmul_rn(r[7], ry); sGeo[8] = __fmul_rn(r[8], rz);
        float aw  = __fadd_rn(__fmul_rn(r[9],  0.84f), 0.01f);
        float a4  = __fadd_rn(__fmul_rn(r[10], 0.84f), 0.01f);
        float a5  = __fadd_rn(__fmul_rn(r[11], 0.84f), 0.01f);
        double trw = sqrt(1.0 - (double)aw);
        double tr4 = sqrt(1.0 - (double)a4);
        double tr5 = sqrt(1.0 - (double)a5);
        double p = 1.0;
        for (int e = 0; e < 16; e++) { sPW[e] = (float)p; p *= trw; }
        p = 1.0;
        for (int e = 0; e < 9;  e++) { sPL[e] = (float)p; p *= tr4; }
        p = 1.0;
        for (int e = 0; e < 9;  e++) { sPH[e] = (float)p; p *= tr5; }
    }
    __syncthreads();

    const float d0 = sGeo[0], d1 = sGeo[1], d2 = sGeo[2];
    const float m0 = sGeo[3], m1 = sGeo[4], m2 = sGeo[5];
    const float s0 = sGeo[6], s1 = sGeo[7], s2v = sGeo[8];

    for (int i = split * TPB + tid; i < NIMG; i += SPLIT * TPB) {
        int pk = g_xyz[i];
        int ix = (pk & 255) - 16;
        int iy = ((pk >> 8) & 255) - 16;
        int iz = (pk >> 16) - 16;

        // --- delay path: replicate the reference's fp32 ops exactly (no FMA) ---
        float img0 = (ix & 1) ? __fsub_rn(__fmul_rn(d0, (float)(ix + 1)), s0)
                              : __fadd_rn(__fmul_rn(d0, (float)ix), s0);
        float img1 = (iy & 1) ? __fsub_rn(__fmul_rn(d1, (float)(iy + 1)), s1)
                              : __fadd_rn(__fmul_rn(d1, (float)iy), s1);
        float img2 = (iz & 1) ? __fsub_rn(__fmul_rn(d2, (float)(iz + 1)), s2v)
                              : __fadd_rn(__fmul_rn(d2, (float)iz), s2v);

        float e0 = __fsub_rn(img0, m0);
        float e1 = __fsub_rn(img1, m1);
        float e2 = __fsub_rn(img2, m2);
        float ss = __fadd_rn(__fadd_rn(__fmul_rn(e0, e0), __fmul_rn(e1, e1)),
                             __fmul_rn(e2, e2));
        float dist  = __fsqrt_rn(ss);
        float delay = __fmul_rn(dist, FSR);
        float di    = ceilf(delay);
        int   t0    = (int)di - PAD;
        if (t0 >= RIR_LENGTH) continue;       // whole window past the buffer (dropped)

        int axy  = abs(ix) + abs(iy);
        int elo2 = (iz >= 0) ? (iz >> 1)       : ((-iz + 1) >> 1);
        int ehi2 = (iz >= 0) ? ((iz + 1) >> 1) : ((-iz) >> 1);
        float att = sPW[axy] * sPL[elo2] * sPH[ehi2];
        float amp = __fdiv_rn(att, dist);
        float frac = __fsub_rn(di, delay);    // in [0, 1)

        if (frac == 0.0f) {                   // degenerate: sinc peak only
            int t = t0 + PAD;                 // = delay_i >= 0
            if (t < RIR_LENGTH) atomicAdd(&srir[t], amp);
            continue;
        }

        float sp  = sinpif(frac);
        float a1  = amp * sp * INV_PI;

        // recurrence seed at k=0: angle = pi*(frac-40)/40 = pi*frac/40 - pi
        float cf, sf;
        sincospif(frac * 0.025f, &sf, &cf);
        float c = -cf;
        float s = -sf;

        int kmax = min(NTAP - 1, RIR_LENGTH - 1 - t0);

        float a1s = a1;                       // (-1)^0
        float x   = frac - (float)PAD;        // never 0 for frac in (0,1)

        #pragma unroll 4
        for (int k = 0; k <= kmax; k++) {
            float win = 0.5f + 0.5f * c;
            float v   = a1s * win * __fdividef(1.0f, x);
            int idx = t0 + k;
            if (idx < 0) idx += RIR_LENGTH;   // JAX negative-index wrap
            atomicAdd(&srir[idx], v);
            float cn = c * CR_STEP - s * SR_STEP;
            s        = s * CR_STEP + c * SR_STEP;
            c        = cn;
            a1s = -a1s;
            x   += 1.0f;
        }
    }
    __syncthreads();

    float* orir = out + b * RIR_LENGTH;
    for (int j = tid; j < RIR_LENGTH; j += TPB) {
        float v = srir[j];
        if (v != 0.0f) atomicAdd(&orir[j], v);
    }
}

// ---------------------------------------------------------------------------
extern "C" void kernel_launch(void* const* d_in, const int* in_sizes, int n_in,
                              void* d_out, int out_size) {
    const float* inp = (const float*)d_in[0];
    float* out = (float*)d_out;

    k_reset<<<1, 1>>>();
    k_build<<<(GRID_TOT + 255) / 256, 256>>>();
    k_init<<<512, 256>>>(inp, out);
    k_main<<<dim3(SPLIT, BATCH), TPB>>>(inp, out);
}